// round 15
// baseline (speedup 1.0000x reference)
#include <cuda_runtime.h>
#include <cuda_fp16.h>
#include <cstdint>
#include <cstddef>

#define T_DIM 4096
#define C_DIM 1024
#define D_DIM 256
#define VOCAB 32000

// Shared tile row stride (fp16): 32 data + 8 pad = 40 (80B rows = 5*16B,
// uint4-aligned; ldmatrix phases conflict-free).
#define SMPAD 40
#define STAGES 3

// ---------------- scratch (__device__ globals: allocation-free rule) --------
__device__ __half g_x_h[T_DIM * C_DIM];               // x fp16
__device__ __half g_wt_h[2][D_DIM * C_DIM];           // W^T fp16, 0=Wq 1=Wk
__device__ float  g_part[4][T_DIM * D_DIM];           // split-K partials
__device__ __half g_q_h[T_DIM * D_DIM];               // q fp16 (pre-scaled 1/256)
__device__ __half g_k_h[T_DIM * D_DIM];               // k fp16
__device__ __half g_ch[(size_t)T_DIM * T_DIM];        // c fp16, lower-tri only
__device__ int    g_idx[T_DIM];

// ---------------------------------------------------------------------------
__global__ void idx_convert_kernel(const int* __restrict__ raw) {
    __shared__ int is64;
    int tid = threadIdx.x;
    if (tid == 0) is64 = 1;
    __syncthreads();
    for (int i = tid; i < 1024; i += blockDim.x)
        if (raw[2 * i + 1] != 0) is64 = 0;
    __syncthreads();
    bool i64 = (is64 != 0);
    for (int i = tid; i < T_DIM; i += blockDim.x)
        g_idx[i] = i64 ? raw[2 * i] : raw[i];
}

__global__ void split_x_kernel(const float* __restrict__ x) {
    const int n4 = T_DIM * C_DIM / 4;
    __half2* H = reinterpret_cast<__half2*>(g_x_h);
    for (int i = blockIdx.x * blockDim.x + threadIdx.x; i < n4;
         i += gridDim.x * blockDim.x) {
        float4 v = reinterpret_cast<const float4*>(x)[i];
        H[2 * i]     = __floats2half2_rn(v.x, v.y);
        H[2 * i + 1] = __floats2half2_rn(v.z, v.w);
    }
}

__global__ void split_w_kernel(const float* __restrict__ Wq,
                               const float* __restrict__ Wk) {
    const float* W = blockIdx.y ? Wk : Wq;
    __half* hi = g_wt_h[blockIdx.y];
    const int total = D_DIM * C_DIM;
    for (int i = blockIdx.x * blockDim.x + threadIdx.x; i < total;
         i += gridDim.x * blockDim.x) {
        int n = i / C_DIM, k = i % C_DIM;
        hi[i] = __float2half_rn(W[(size_t)k * D_DIM + n]);  // store transposed
    }
}

// ---------------------------------------------------------------------------
__device__ __forceinline__ void mma16816(float* d, const uint32_t* a,
                                         const uint32_t* b) {
    asm volatile(
        "mma.sync.aligned.m16n8k16.row.col.f32.f16.f16.f32 "
        "{%0,%1,%2,%3},{%4,%5,%6,%7},{%8,%9},{%0,%1,%2,%3};"
        : "+f"(d[0]), "+f"(d[1]), "+f"(d[2]), "+f"(d[3])
        : "r"(a[0]), "r"(a[1]), "r"(a[2]), "r"(a[3]), "r"(b[0]), "r"(b[1]));
}

__device__ __forceinline__ uint32_t smem_u32(const void* p) {
    return (uint32_t)__cvta_generic_to_shared(p);
}
__device__ __forceinline__ void ldsm4(uint32_t* r, const void* p) {
    asm volatile("ldmatrix.sync.aligned.m8n8.x4.shared.b16 {%0,%1,%2,%3}, [%4];"
                 : "=r"(r[0]), "=r"(r[1]), "=r"(r[2]), "=r"(r[3])
                 : "r"(smem_u32(p)));
}

__device__ __forceinline__ void cp16(void* smem, const void* gmem) {
    asm volatile("cp.async.cg.shared.global [%0], [%1], 16;"
                 :: "r"(smem_u32(smem)), "l"(gmem));
}
__device__ __forceinline__ void cp_commit() {
    asm volatile("cp.async.commit_group;");
}
template <int N>
__device__ __forceinline__ void cp_wait() {
    asm volatile("cp.async.wait_group %0;" :: "n"(N));
}

// One pipeline stage: 15360 B (A 128x40, B 64x40 fp16)
struct Tiles {
    __half As_h[128][SMPAD];
    __half Bs_h[64][SMPAD];
};

// Compute one BK=32 slab. 8 warps (4x2), warp tile 32x32, single-term fp16.
__device__ __forceinline__ void compute_slab(const Tiles& st, int wm, int wn,
                                             int lane, float acc[2][4][4]) {
    const int ra = (lane & 7) + ((lane >> 3) & 1) * 8;
    const int ca = (lane >> 4) * 8;
    const int rb = (lane & 7) + (lane >> 4) * 8;
    const int cb = ((lane >> 3) & 1) * 8;

    #pragma unroll
    for (int h = 0; h < 2; h++) {
        const int s16 = h * 16;
        uint32_t ah[2][4], bh[4][2];
        #pragma unroll
        for (int ms = 0; ms < 2; ms++) {
            int r = wm * 32 + ms * 16 + ra;
            ldsm4(ah[ms], &st.As_h[r][s16 + ca]);
        }
        #pragma unroll
        for (int pr = 0; pr < 2; pr++) {
            int r = wn * 32 + pr * 16 + rb;
            uint32_t q[4];
            ldsm4(q, &st.Bs_h[r][s16 + cb]);
            bh[2 * pr][0] = q[0]; bh[2 * pr][1] = q[1];
            bh[2 * pr + 1][0] = q[2]; bh[2 * pr + 1][1] = q[3];
        }
        #pragma unroll
        for (int ms = 0; ms < 2; ms++)
            #pragma unroll
            for (int ns = 0; ns < 4; ns++)
                mma16816(acc[ms][ns], ah[ms], bh[ns]);
    }
}

__device__ __forceinline__ void load_slab(Tiles& st, int tid,
                                          const __half* a, size_t ldA,
                                          const __half* bH, size_t ldB,
                                          int k0) {
    #pragma unroll
    for (int s = 0; s < 2; s++) {
        int idx = tid + s * 256;
        int r = idx >> 2, cw = (idx & 3) * 8;
        cp16(&st.As_h[r][cw], &a[(size_t)r * ldA + k0 + cw]);
    }
    {
        int r = tid >> 2, cw = (tid & 3) * 8;
        cp16(&st.Bs_h[r][cw], &bH[(size_t)r * ldB + k0 + cw]);
    }
    cp_commit();
}

template <int KT>
__device__ __forceinline__ void gemm_mainloop(
    Tiles* stages, int tid, int wm, int wn, int lane,
    const __half* a, size_t ldA, const __half* bH, size_t ldB,
    float acc[2][4][4]) {

    load_slab(stages[0], tid, a, ldA, bH, ldB, 0);
    if (KT > 1) load_slab(stages[1], tid, a, ldA, bH, ldB, 32);

    for (int i = 0; i < KT; i++) {
        cp_wait<1>();
        __syncthreads();
        int nx = i + STAGES - 1;
        if (nx < KT)
            load_slab(stages[nx % STAGES], tid, a, ldA, bH, ldB, nx * 32);
        else
            cp_commit();
        compute_slab(stages[i % STAGES], wm, wn, lane, acc);
    }
}

// ---------------------------------------------------------------------------
// qk GEMM, split-K x2: grid (4, 32, 4); which = z&1, K offset = (z>>1)*512.
// ---------------------------------------------------------------------------
__global__ __launch_bounds__(256, 4) void qk_mma_kernel() {
    extern __shared__ Tiles stages[];   // [STAGES]

    const int z = blockIdx.z;
    const int which = z & 1;
    const int koff = (z >> 1) * 512;
    const int m0 = blockIdx.y * 128;
    const int n0 = blockIdx.x * 64;

    const int tid  = threadIdx.x;
    const int warp = tid >> 5, lane = tid & 31;
    const int wm = warp >> 1, wn = warp & 1;
    const int g = lane >> 2, tg = lane & 3;

    float acc[2][4][4] = {};
    gemm_mainloop<16>(
        stages, tid, wm, wn, lane,
        g_x_h + (size_t)m0 * C_DIM + koff, C_DIM,
        g_wt_h[which] + (size_t)n0 * C_DIM + koff, C_DIM,
        acc);

    float* dst = g_part[z];
    #pragma unroll
    for (int ms = 0; ms < 2; ms++)
        #pragma unroll
        for (int ns = 0; ns < 4; ns++) {
            int m = m0 + wm * 32 + ms * 16 + g;
            int n = n0 + wn * 32 + ns * 8 + tg * 2;
            float* c = acc[ms][ns];
            *reinterpret_cast<float2*>(&dst[(size_t)m * D_DIM + n]) =
                make_float2(c[0], c[1]);
            *reinterpret_cast<float2*>(&dst[(size_t)(m + 8) * D_DIM + n]) =
                make_float2(c[2], c[3]);
        }
}

// Reduce split-K partials: q = (p0+p2)/256 (scale folded), k = p1+p3.
__global__ void qk_reduce_kernel() {
    const int n4 = T_DIM * D_DIM / 4;
    const float s = 1.0f / 256.0f;
    const float4* P0 = reinterpret_cast<const float4*>(g_part[0]);
    const float4* P1 = reinterpret_cast<const float4*>(g_part[1]);
    const float4* P2 = reinterpret_cast<const float4*>(g_part[2]);
    const float4* P3 = reinterpret_cast<const float4*>(g_part[3]);
    __half2* QH = reinterpret_cast<__half2*>(g_q_h);
    __half2* KH = reinterpret_cast<__half2*>(g_k_h);
    for (int i = blockIdx.x * blockDim.x + threadIdx.x; i < n4;
         i += gridDim.x * blockDim.x) {
        float4 a = P0[i], b = P2[i];
        QH[2 * i]     = __floats2half2_rn((a.x + b.x) * s, (a.y + b.y) * s);
        QH[2 * i + 1] = __floats2half2_rn((a.z + b.z) * s, (a.w + b.w) * s);
        a = P1[i]; b = P3[i];
        KH[2 * i]     = __floats2half2_rn(a.x + b.x, a.y + b.y);
        KH[2 * i + 1] = __floats2half2_rn(a.z + b.z, a.w + b.w);
    }
}

// ---------------------------------------------------------------------------
// c GEMM: c = q_scaled @ k^T -> fp16, triangular grid (1056 live tiles).
// ---------------------------------------------------------------------------
__global__ __launch_bounds__(256, 4) void c_mma_kernel() {
    extern __shared__ Tiles stages[];   // [STAGES]

    const int bid = blockIdx.x;
    int by = (int)((sqrtf(4.0f * bid + 1.0f) - 1.0f) * 0.5f);
    while (by * by + by > bid) by--;
    while ((by + 1) * (by + 1) + (by + 1) <= bid) by++;
    const int bx = bid - (by * by + by);

    const int t0 = by * 128;
    const int j0 = bx * 64;

    const int tid  = threadIdx.x;
    const int warp = tid >> 5, lane = tid & 31;
    const int wm = warp >> 1, wn = warp & 1;
    const int g = lane >> 2, tg = lane & 3;

    float acc[2][4][4] = {};
    gemm_mainloop<D_DIM / 32>(
        stages, tid, wm, wn, lane,
        g_q_h + (size_t)t0 * D_DIM, D_DIM,
        g_k_h + (size_t)j0 * D_DIM, D_DIM,
        acc);

    #pragma unroll
    for (int ms = 0; ms < 2; ms++)
        #pragma unroll
        for (int ns = 0; ns < 4; ns++) {
            int m = t0 + wm * 32 + ms * 16 + g;
            int n = j0 + wn * 32 + ns * 8 + tg * 2;
            float* c = acc[ms][ns];
            *reinterpret_cast<__half2*>(&g_ch[(size_t)m * T_DIM + n]) =
                __floats2half2_rn(c[0], c[1]);
            *reinterpret_cast<__half2*>(&g_ch[(size_t)(m + 8) * T_DIM + n]) =
                __floats2half2_rn(c[2], c[3]);
        }
}

// ---------------------------------------------------------------------------
// Persistent scatter: 444 CTAs (3/SM) loop over 8192 (row, vocab-half) units.
// No launch waves/tail; DRAM write stream stays saturated; halves of the same
// c row land on adjacent CTAs concurrently (L2 reuse).
// ---------------------------------------------------------------------------
#define HALF_V (VOCAB / 2)
#define SCATTER_GRID 444

__global__ __launch_bounds__(640) void scatter_kernel(float* __restrict__ out) {
    extern __shared__ float hist[];  // HALF_V floats = 64000 B
    const int tid = threadIdx.x;
    const int nt = blockDim.x;
    const int nunits = 2 * T_DIM;

    for (int u = blockIdx.x; u < nunits; u += gridDim.x) {
        const int t    = u >> 1;
        const int half = u & 1;
        const int vlo  = half * HALF_V;

        float4* h4 = reinterpret_cast<float4*>(hist);
        const float4 z4 = make_float4(0.f, 0.f, 0.f, 0.f);
        for (int i = tid; i < HALF_V / 4; i += nt) h4[i] = z4;
        __syncthreads();

        const __half2* crow2 =
            reinterpret_cast<const __half2*>(&g_ch[(size_t)t * T_DIM]);
        const int2* idx2 = reinterpret_cast<const int2*>(g_idx);
        const int npair = (t + 2) >> 1;          // pairs covering j <= t
        for (int p = tid; p < npair; p += nt) {
            __half2 v = __ldcs(&crow2[p]);
            int2 ij = idx2[p];
            unsigned v0 = (unsigned)(ij.x - vlo);
            if (v0 < (unsigned)HALF_V) atomicAdd(&hist[v0], __low2float(v));
            if (2 * p + 1 <= t) {
                unsigned v1 = (unsigned)(ij.y - vlo);
                if (v1 < (unsigned)HALF_V) atomicAdd(&hist[v1], __high2float(v));
            }
        }
        __syncthreads();

        float4* o4 = reinterpret_cast<float4*>(out + (size_t)t * VOCAB + vlo);
        for (int i = tid; i < HALF_V / 4; i += nt) __stcs(&o4[i], h4[i]);
        __syncthreads();   // protect hist before next unit's zero phase
    }
}

// ---------------------------------------------------------------------------
extern "C" void kernel_launch(void* const* d_in, const int* in_sizes, int n_in,
                              void* d_out, int out_size) {
    const float* x      = (const float*)d_in[0];
    const int*   idxraw = (const int*)d_in[1];
    const float* Wq     = (const float*)d_in[2];
    const float* Wk     = (const float*)d_in[3];
    float*       out    = (float*)d_out;
    (void)in_sizes; (void)n_in; (void)out_size;

    const int PIPE_SMEM = STAGES * (int)sizeof(Tiles);   // 46080 B

    idx_convert_kernel<<<1, 256>>>(idxraw);
    split_x_kernel<<<1024, 256>>>(x);
    split_w_kernel<<<dim3(64, 2), 256>>>(Wq, Wk);

    cudaFuncSetAttribute(qk_mma_kernel,
                         cudaFuncAttributeMaxDynamicSharedMemorySize, PIPE_SMEM);
    qk_mma_kernel<<<dim3(4, 32, 4), 256, PIPE_SMEM>>>();

    qk_reduce_kernel<<<512, 256>>>();

    cudaFuncSetAttribute(c_mma_kernel,
                         cudaFuncAttributeMaxDynamicSharedMemorySize, PIPE_SMEM);
    c_mma_kernel<<<1056, 256, PIPE_SMEM>>>();

    cudaFuncSetAttribute(scatter_kernel,
                         cudaFuncAttributeMaxDynamicSharedMemorySize,
                         HALF_V * (int)sizeof(float));
    scatter_kernel<<<SCATTER_GRID, 640, HALF_V * sizeof(float)>>>(out);
}

// round 16
// speedup vs baseline: 1.0854x; 1.0854x over previous
#include <cuda_runtime.h>
#include <cuda_fp16.h>
#include <cstdint>
#include <cstddef>

#define T_DIM 4096
#define C_DIM 1024
#define D_DIM 256
#define VOCAB 32000

// Shared tile row stride (fp16): 32 data + 8 pad = 40 (80B rows = 5*16B,
// uint4-aligned; ldmatrix phases conflict-free).
#define SMPAD 40
#define STAGES 3

// ---------------- scratch (__device__ globals: allocation-free rule) --------
__device__ __half g_x_h[T_DIM * C_DIM];               // x fp16
__device__ __half g_wt_h[2][D_DIM * C_DIM];           // W^T fp16, 0=Wq 1=Wk
__device__ float  g_part[4][T_DIM * D_DIM];           // split-K partials
__device__ __half g_q_h[T_DIM * D_DIM];               // q fp16 (pre-scaled 1/256)
__device__ __half g_k_h[T_DIM * D_DIM];               // k fp16
__device__ __half g_ch[(size_t)T_DIM * T_DIM];        // c fp16, lower-tri only
__device__ int    g_idx[T_DIM];

// ---------------------------------------------------------------------------
// Fused prep: one launch does x->fp16 (blocks 0..1023), W^T->fp16
// (blocks 1024..1151, 64 per matrix), idx normalize (block 1152).
// ---------------------------------------------------------------------------
__global__ void prep_kernel(const float* __restrict__ x,
                            const int* __restrict__ idxraw,
                            const float* __restrict__ Wq,
                            const float* __restrict__ Wk) {
    const int bid = blockIdx.x;
    const int tid = threadIdx.x;

    if (bid < 1024) {
        // x conversion: 1M float4 chunks over 1024 blocks
        const int n4 = T_DIM * C_DIM / 4;
        __half2* H = reinterpret_cast<__half2*>(g_x_h);
        for (int i = bid * 256 + tid; i < n4; i += 1024 * 256) {
            float4 v = reinterpret_cast<const float4*>(x)[i];
            H[2 * i]     = __floats2half2_rn(v.x, v.y);
            H[2 * i + 1] = __floats2half2_rn(v.z, v.w);
        }
    } else if (bid < 1152) {
        // W transpose + convert: 64 blocks per matrix
        const int lb = bid - 1024;
        const int which = lb >> 6;
        const float* W = which ? Wk : Wq;
        __half* hi = g_wt_h[which];
        const int total = D_DIM * C_DIM;
        for (int i = (lb & 63) * 256 + tid; i < total; i += 64 * 256) {
            int n = i / C_DIM, k = i % C_DIM;
            hi[i] = __float2half_rn(W[(size_t)k * D_DIM + n]);
        }
    } else {
        // idx normalize (int32 vs int64 sniff)
        __shared__ int is64;
        if (tid == 0) is64 = 1;
        __syncthreads();
        for (int i = tid; i < 1024; i += blockDim.x)
            if (idxraw[2 * i + 1] != 0) is64 = 0;
        __syncthreads();
        bool i64 = (is64 != 0);
        for (int i = tid; i < T_DIM; i += blockDim.x)
            g_idx[i] = i64 ? idxraw[2 * i] : idxraw[i];
    }
}

// ---------------------------------------------------------------------------
__device__ __forceinline__ void mma16816(float* d, const uint32_t* a,
                                         const uint32_t* b) {
    asm volatile(
        "mma.sync.aligned.m16n8k16.row.col.f32.f16.f16.f32 "
        "{%0,%1,%2,%3},{%4,%5,%6,%7},{%8,%9},{%0,%1,%2,%3};"
        : "+f"(d[0]), "+f"(d[1]), "+f"(d[2]), "+f"(d[3])
        : "r"(a[0]), "r"(a[1]), "r"(a[2]), "r"(a[3]), "r"(b[0]), "r"(b[1]));
}

__device__ __forceinline__ uint32_t smem_u32(const void* p) {
    return (uint32_t)__cvta_generic_to_shared(p);
}
__device__ __forceinline__ void ldsm4(uint32_t* r, const void* p) {
    asm volatile("ldmatrix.sync.aligned.m8n8.x4.shared.b16 {%0,%1,%2,%3}, [%4];"
                 : "=r"(r[0]), "=r"(r[1]), "=r"(r[2]), "=r"(r[3])
                 : "r"(smem_u32(p)));
}

__device__ __forceinline__ void cp16(void* smem, const void* gmem) {
    asm volatile("cp.async.cg.shared.global [%0], [%1], 16;"
                 :: "r"(smem_u32(smem)), "l"(gmem));
}
__device__ __forceinline__ void cp_commit() {
    asm volatile("cp.async.commit_group;");
}
template <int N>
__device__ __forceinline__ void cp_wait() {
    asm volatile("cp.async.wait_group %0;" :: "n"(N));
}

// One pipeline stage: 15360 B (A 128x40, B 64x40 fp16)
struct Tiles {
    __half As_h[128][SMPAD];
    __half Bs_h[64][SMPAD];
};

// Compute one BK=32 slab. 8 warps (4x2), warp tile 32x32, single-term fp16.
__device__ __forceinline__ void compute_slab(const Tiles& st, int wm, int wn,
                                             int lane, float acc[2][4][4]) {
    const int ra = (lane & 7) + ((lane >> 3) & 1) * 8;
    const int ca = (lane >> 4) * 8;
    const int rb = (lane & 7) + (lane >> 4) * 8;
    const int cb = ((lane >> 3) & 1) * 8;

    #pragma unroll
    for (int h = 0; h < 2; h++) {
        const int s16 = h * 16;
        uint32_t ah[2][4], bh[4][2];
        #pragma unroll
        for (int ms = 0; ms < 2; ms++) {
            int r = wm * 32 + ms * 16 + ra;
            ldsm4(ah[ms], &st.As_h[r][s16 + ca]);
        }
        #pragma unroll
        for (int pr = 0; pr < 2; pr++) {
            int r = wn * 32 + pr * 16 + rb;
            uint32_t q[4];
            ldsm4(q, &st.Bs_h[r][s16 + cb]);
            bh[2 * pr][0] = q[0]; bh[2 * pr][1] = q[1];
            bh[2 * pr + 1][0] = q[2]; bh[2 * pr + 1][1] = q[3];
        }
        #pragma unroll
        for (int ms = 0; ms < 2; ms++)
            #pragma unroll
            for (int ns = 0; ns < 4; ns++)
                mma16816(acc[ms][ns], ah[ms], bh[ns]);
    }
}

__device__ __forceinline__ void load_slab(Tiles& st, int tid,
                                          const __half* a, size_t ldA,
                                          const __half* bH, size_t ldB,
                                          int k0) {
    #pragma unroll
    for (int s = 0; s < 2; s++) {
        int idx = tid + s * 256;
        int r = idx >> 2, cw = (idx & 3) * 8;
        cp16(&st.As_h[r][cw], &a[(size_t)r * ldA + k0 + cw]);
    }
    {
        int r = tid >> 2, cw = (tid & 3) * 8;
        cp16(&st.Bs_h[r][cw], &bH[(size_t)r * ldB + k0 + cw]);
    }
    cp_commit();
}

template <int KT>
__device__ __forceinline__ void gemm_mainloop(
    Tiles* stages, int tid, int wm, int wn, int lane,
    const __half* a, size_t ldA, const __half* bH, size_t ldB,
    float acc[2][4][4]) {

    load_slab(stages[0], tid, a, ldA, bH, ldB, 0);
    if (KT > 1) load_slab(stages[1], tid, a, ldA, bH, ldB, 32);

    for (int i = 0; i < KT; i++) {
        cp_wait<1>();
        __syncthreads();
        int nx = i + STAGES - 1;
        if (nx < KT)
            load_slab(stages[nx % STAGES], tid, a, ldA, bH, ldB, nx * 32);
        else
            cp_commit();
        compute_slab(stages[i % STAGES], wm, wn, lane, acc);
    }
}

// ---------------------------------------------------------------------------
// qk GEMM, split-K x2: grid (4, 32, 4); which = z&1, K offset = (z>>1)*512.
// ---------------------------------------------------------------------------
__global__ __launch_bounds__(256, 4) void qk_mma_kernel() {
    extern __shared__ Tiles stages[];   // [STAGES]

    const int z = blockIdx.z;
    const int which = z & 1;
    const int koff = (z >> 1) * 512;
    const int m0 = blockIdx.y * 128;
    const int n0 = blockIdx.x * 64;

    const int tid  = threadIdx.x;
    const int warp = tid >> 5, lane = tid & 31;
    const int wm = warp >> 1, wn = warp & 1;
    const int g = lane >> 2, tg = lane & 3;

    float acc[2][4][4] = {};
    gemm_mainloop<16>(
        stages, tid, wm, wn, lane,
        g_x_h + (size_t)m0 * C_DIM + koff, C_DIM,
        g_wt_h[which] + (size_t)n0 * C_DIM + koff, C_DIM,
        acc);

    float* dst = g_part[z];
    #pragma unroll
    for (int ms = 0; ms < 2; ms++)
        #pragma unroll
        for (int ns = 0; ns < 4; ns++) {
            int m = m0 + wm * 32 + ms * 16 + g;
            int n = n0 + wn * 32 + ns * 8 + tg * 2;
            float* c = acc[ms][ns];
            *reinterpret_cast<float2*>(&dst[(size_t)m * D_DIM + n]) =
                make_float2(c[0], c[1]);
            *reinterpret_cast<float2*>(&dst[(size_t)(m + 8) * D_DIM + n]) =
                make_float2(c[2], c[3]);
        }
}

// Reduce split-K partials: q = (p0+p2)/256 (scale folded), k = p1+p3.
__global__ void qk_reduce_kernel() {
    const int n4 = T_DIM * D_DIM / 4;
    const float s = 1.0f / 256.0f;
    const float4* P0 = reinterpret_cast<const float4*>(g_part[0]);
    const float4* P1 = reinterpret_cast<const float4*>(g_part[1]);
    const float4* P2 = reinterpret_cast<const float4*>(g_part[2]);
    const float4* P3 = reinterpret_cast<const float4*>(g_part[3]);
    __half2* QH = reinterpret_cast<__half2*>(g_q_h);
    __half2* KH = reinterpret_cast<__half2*>(g_k_h);
    for (int i = blockIdx.x * blockDim.x + threadIdx.x; i < n4;
         i += gridDim.x * blockDim.x) {
        float4 a = P0[i], b = P2[i];
        QH[2 * i]     = __floats2half2_rn((a.x + b.x) * s, (a.y + b.y) * s);
        QH[2 * i + 1] = __floats2half2_rn((a.z + b.z) * s, (a.w + b.w) * s);
        a = P1[i]; b = P3[i];
        KH[2 * i]     = __floats2half2_rn(a.x + b.x, a.y + b.y);
        KH[2 * i + 1] = __floats2half2_rn(a.z + b.z, a.w + b.w);
    }
}

// ---------------------------------------------------------------------------
// c GEMM: c = q_scaled @ k^T -> fp16, triangular grid (1056 live tiles).
// ---------------------------------------------------------------------------
__global__ __launch_bounds__(256, 4) void c_mma_kernel() {
    extern __shared__ Tiles stages[];   // [STAGES]

    const int bid = blockIdx.x;
    int by = (int)((sqrtf(4.0f * bid + 1.0f) - 1.0f) * 0.5f);
    while (by * by + by > bid) by--;
    while ((by + 1) * (by + 1) + (by + 1) <= bid) by++;
    const int bx = bid - (by * by + by);

    const int t0 = by * 128;
    const int j0 = bx * 64;

    const int tid  = threadIdx.x;
    const int warp = tid >> 5, lane = tid & 31;
    const int wm = warp >> 1, wn = warp & 1;
    const int g = lane >> 2, tg = lane & 3;

    float acc[2][4][4] = {};
    gemm_mainloop<D_DIM / 32>(
        stages, tid, wm, wn, lane,
        g_q_h + (size_t)t0 * D_DIM, D_DIM,
        g_k_h + (size_t)j0 * D_DIM, D_DIM,
        acc);

    #pragma unroll
    for (int ms = 0; ms < 2; ms++)
        #pragma unroll
        for (int ns = 0; ns < 4; ns++) {
            int m = t0 + wm * 32 + ms * 16 + g;
            int n = j0 + wn * 32 + ns * 8 + tg * 2;
            float* c = acc[ms][ns];
            *reinterpret_cast<__half2*>(&g_ch[(size_t)m * T_DIM + n]) =
                __floats2half2_rn(c[0], c[1]);
            *reinterpret_cast<__half2*>(&g_ch[(size_t)(m + 8) * T_DIM + n]) =
                __floats2half2_rn(c[2], c[3]);
        }
}

// ---------------------------------------------------------------------------
// scatter (R14 winner): each CTA owns (row t, vocab half). 640 threads,
// 64KB hist -> 3 CTAs/SM; wave-scheduled grid balances unit costs.
// ---------------------------------------------------------------------------
#define HALF_V (VOCAB / 2)

__global__ __launch_bounds__(640) void scatter_kernel(float* __restrict__ out) {
    extern __shared__ float hist[];  // HALF_V floats = 64000 B
    const int t    = blockIdx.x >> 1;
    const int half = blockIdx.x & 1;
    const int vlo  = half * HALF_V;
    const int tid = threadIdx.x;
    const int nt = blockDim.x;

    float4* h4 = reinterpret_cast<float4*>(hist);
    const float4 z4 = make_float4(0.f, 0.f, 0.f, 0.f);
    for (int i = tid; i < HALF_V / 4; i += nt) h4[i] = z4;
    __syncthreads();

    const __half2* crow2 =
        reinterpret_cast<const __half2*>(&g_ch[(size_t)t * T_DIM]);
    const int2* idx2 = reinterpret_cast<const int2*>(g_idx);
    const int npair = (t + 2) >> 1;          // pairs covering j <= t
    for (int p = tid; p < npair; p += nt) {
        __half2 v = __ldcs(&crow2[p]);
        int2 ij = idx2[p];
        unsigned v0 = (unsigned)(ij.x - vlo);
        if (v0 < (unsigned)HALF_V) atomicAdd(&hist[v0], __low2float(v));
        if (2 * p + 1 <= t) {
            unsigned v1 = (unsigned)(ij.y - vlo);
            if (v1 < (unsigned)HALF_V) atomicAdd(&hist[v1], __high2float(v));
        }
    }
    __syncthreads();

    float4* o4 = reinterpret_cast<float4*>(out + (size_t)t * VOCAB + vlo);
    for (int i = tid; i < HALF_V / 4; i += nt) __stcs(&o4[i], h4[i]);
}

// ---------------------------------------------------------------------------
extern "C" void kernel_launch(void* const* d_in, const int* in_sizes, int n_in,
                              void* d_out, int out_size) {
    const float* x      = (const float*)d_in[0];
    const int*   idxraw = (const int*)d_in[1];
    const float* Wq     = (const float*)d_in[2];
    const float* Wk     = (const float*)d_in[3];
    float*       out    = (float*)d_out;
    (void)in_sizes; (void)n_in; (void)out_size;

    const int PIPE_SMEM = STAGES * (int)sizeof(Tiles);   // 46080 B

    prep_kernel<<<1153, 256>>>(x, idxraw, Wq, Wk);

    cudaFuncSetAttribute(qk_mma_kernel,
                         cudaFuncAttributeMaxDynamicSharedMemorySize, PIPE_SMEM);
    qk_mma_kernel<<<dim3(4, 32, 4), 256, PIPE_SMEM>>>();

    qk_reduce_kernel<<<512, 256>>>();

    cudaFuncSetAttribute(c_mma_kernel,
                         cudaFuncAttributeMaxDynamicSharedMemorySize, PIPE_SMEM);
    c_mma_kernel<<<1056, 256, PIPE_SMEM>>>();

    cudaFuncSetAttribute(scatter_kernel,
                         cudaFuncAttributeMaxDynamicSharedMemorySize,
                         HALF_V * (int)sizeof(float));
    scatter_kernel<<<2 * T_DIM, 640, HALF_V * sizeof(float)>>>(out);
}